// round 2
// baseline (speedup 1.0000x reference)
#include <cuda_runtime.h>
#include <cuda_bf16.h>

// Gemma4VisionPooler: 2x2 segment-mean pool (B=16, L=4096 -> 1024, H=1152) * sqrt(H)
// Gather-side design: tiny inverse-index kernel + streaming pool kernel.
// Positions may be int32 or int64 depending on JAX x64 config -> detect at runtime.

#define BATCH  16
#define LIN    4096
#define HID    1152
#define OUTLEN 1024
#define KPOOL  2          // sqrt(LIN/OUTLEN)
#define SLOTS  8          // capacity per segment (expected 4)
#define H4     (HID / 4)  // 288 float4 per row

// Scratch (allocation-free rule: __device__ globals)
__device__ int g_cnt[BATCH * OUTLEN];
__device__ int g_idx[BATCH * OUTLEN * SLOTS];

// ---------------------------------------------------------------------------
// Kernel 1: dtype-detect + per-batch max_x + inverse index build.
// One block per batch, 256 threads.
// ---------------------------------------------------------------------------
__global__ void build_index_kernel(const int* __restrict__ p32) {
    const int b   = blockIdx.x;
    const int tid = threadIdx.x;
    __shared__ int smax;
    __shared__ int s_is32;   // 1 if positions are int32, 0 if int64

    if (tid == 0) { smax = 0; s_is32 = 0; }

    // zero this batch's counters
    for (int s = tid; s < OUTLEN; s += blockDim.x) g_cnt[b * OUTLEN + s] = 0;
    __syncthreads();

    // --- dtype detection over this batch's region, interpreted as int32 pairs.
    // int64 layout: odd 32-bit words are high words: 0 (nonneg) or -1 (neg).
    // int32 layout: odd words are y-coordinates, which exceed 0 somewhere.
    {
        int found = 0;
        const int* base = p32 + (long long)b * LIN * 2;  // int32-pair view span
        for (int i = tid * 2 + 1; i < LIN * 2; i += blockDim.x * 2)
            if (base[i] > 0) found = 1;
        if (found) atomicOr(&s_is32, 1);
    }
    __syncthreads();
    const int is32 = s_is32;

    // --- decode helper via lambdas is awkward in __global__; inline loops.
    // Pass 1: max over clamped x
    int lmax = 0;
    for (int l = tid; l < LIN; l += blockDim.x) {
        int xi;
        if (is32) {
            xi = p32[((long long)b * LIN + l) * 2];
        } else {
            const long long idx4 = ((long long)b * LIN + l) * 4;  // int32 words of int64 pair
            int lo = p32[idx4 + 0];
            int hi = p32[idx4 + 1];
            xi = (hi < 0) ? -1 : lo;   // negative int64 -> clamps to 0 below
        }
        if (xi < 0) xi = 0;
        lmax = lmax > xi ? lmax : xi;
    }
    atomicMax(&smax, lmax);
    __syncthreads();

    const int wseg = (smax + 1) / KPOOL;   // (max_x+1) // k

    // Pass 2: scatter input row index into its segment's slot list
    for (int l = tid; l < LIN; l += blockDim.x) {
        int xi, yi;
        if (is32) {
            xi = p32[((long long)b * LIN + l) * 2 + 0];
            yi = p32[((long long)b * LIN + l) * 2 + 1];
        } else {
            const long long idx4 = ((long long)b * LIN + l) * 4;
            int xlo = p32[idx4 + 0], xhi = p32[idx4 + 1];
            int ylo = p32[idx4 + 2], yhi = p32[idx4 + 3];
            xi = (xhi < 0) ? -1 : xlo;
            yi = (yhi < 0) ? -1 : ylo;
        }
        if (xi < 0) xi = 0;
        if (yi < 0) yi = 0;
        int seg = xi / KPOOL + wseg * (yi / KPOOL);
        if (seg < 0) seg = 0;
        if (seg >= OUTLEN) seg = OUTLEN - 1;   // safety: never corrupt scratch
        int slot = atomicAdd(&g_cnt[b * OUTLEN + seg], 1);
        if (slot < SLOTS) g_idx[(b * OUTLEN + seg) * SLOTS + slot] = l;
    }
}

// ---------------------------------------------------------------------------
// Kernel 2: gather + mean + scale. One block per (batch, segment), 288 threads,
// each thread owns one float4 column of the 1152-wide row.
// ---------------------------------------------------------------------------
__global__ void __launch_bounds__(H4) pool_kernel(
    const float4* __restrict__ in,
    const unsigned char* __restrict__ pad,
    float4* __restrict__ out,
    float* __restrict__ mask_out)   // nullptr if harness buffer has no mask tail
{
    const int bs  = blockIdx.x;          // b * OUTLEN + seg
    const int b   = bs / OUTLEN;
    const int tid = threadIdx.x;

    const int cnt = g_cnt[bs];
    const int n   = cnt < SLOTS ? cnt : SLOTS;

    float4 acc = make_float4(0.f, 0.f, 0.f, 0.f);
#pragma unroll 4
    for (int j = 0; j < n; j++) {
        int l = g_idx[bs * SLOTS + j];
        if (!pad[(long long)b * LIN + l]) {   // zero padded patches pre-pool
            float4 v = in[((long long)b * LIN + l) * H4 + tid];
            acc.x += v.x; acc.y += v.y; acc.z += v.z; acc.w += v.w;
        }
    }

    // pooled = sum / k^2, then * sqrt(H) :  sqrt(1152)/4
    const float SCALE = 8.4852813742385702928f;
    acc.x *= SCALE; acc.y *= SCALE; acc.z *= SCALE; acc.w *= SCALE;

    out[(long long)bs * H4 + tid] = acc;

    if (mask_out != nullptr && tid == 0)
        mask_out[bs] = (cnt > 0) ? 1.0f : 0.0f;
}

// ---------------------------------------------------------------------------
extern "C" void kernel_launch(void* const* d_in, const int* in_sizes, int n_in,
                              void* d_out, int out_size)
{
    const float*         hs  = (const float*)d_in[0];          // [B, L, H] f32
    const int*           pos = (const int*)d_in[1];            // [B, L, 2] i32 or i64
    const unsigned char* pad = (const unsigned char*)d_in[2];  // [B, L] bool

    float* out = (float*)d_out;

    const long long hs_elems = (long long)BATCH * OUTLEN * HID;
    float* mask_out = nullptr;
    if ((long long)out_size >= hs_elems + (long long)BATCH * OUTLEN)
        mask_out = out + hs_elems;

    build_index_kernel<<<BATCH, 256>>>(pos);
    pool_kernel<<<BATCH * OUTLEN, H4>>>(
        (const float4*)hs, pad, (float4*)out, mask_out);
}